// round 15
// baseline (speedup 1.0000x reference)
#include <cuda_runtime.h>
#include <cstdint>

#define DIMN 384
#define NP 192                    // logical uint2 slots per B row (full K)
#define PSB 52                    // B pitch in uint2 (48 data + 4 pad)
#define A4_CNT 3072               // uint4 per 32-row A block (full K)
#define A4_PER_CHUNK 768          // uint4 per K=96 chunk
#define ABYTES_C (A4_PER_CHUNK * 16)      // 12288
#define BPAD_CHUNK (32 * PSB)
#define BBYTES_C (BPAD_CHUNK * 8) // 13312
#define STAGE_B (ABYTES_C + BBYTES_C)     // 25600
#define SMEM_GEMM (2 * STAGE_B)   // 51200 -> 4 CTAs/SM resident

// Scratch (no cudaMalloc allowed)
__device__ __align__(16) uint4 g_v1p4[32 * A4_CNT];
__device__ __align__(16) uint4 g_tp4[32 * A4_CNT];
__device__ __align__(16) uint2 g_lwp[12 * 4 * BPAD_CHUNK];
__device__ __align__(16) uint2 g_Ptp[12 * 4 * BPAD_CHUNK];
__device__ float g_cbar[DIMN];
// per-rowblock producer/consumer flags (monotonic -> graph-replay safe)
__device__ unsigned long long g_g0done[32];
__device__ unsigned long long g_g1arr[32];

__device__ __forceinline__ uint32_t f2tf32(float x) {
    uint32_t y; asm("cvt.rna.tf32.f32 %0, %1;" : "=r"(y) : "f"(x)); return y;
}
__device__ __forceinline__ uint32_t smem_u32(const void* p) {
    uint32_t a;
    asm("{ .reg .u64 t; cvta.to.shared.u64 t, %1; cvt.u32.u64 %0, t; }" : "=r"(a) : "l"(p));
    return a;
}
__device__ __forceinline__ void mbar_init(uint32_t mb, uint32_t cnt) {
    asm volatile("mbarrier.init.shared.b64 [%0], %1;" :: "r"(mb), "r"(cnt) : "memory");
}
__device__ __forceinline__ void mbar_expect(uint32_t mb, uint32_t tx) {
    asm volatile("mbarrier.arrive.expect_tx.shared.b64 _, [%0], %1;" :: "r"(mb), "r"(tx) : "memory");
}
#define MBAR_WAIT(mb, ph) do { \
    asm volatile("{\n\t.reg .pred P1;\n\t" \
        "WAIT_LOOP_%=:\n\t" \
        "mbarrier.try_wait.parity.acquire.cta.shared::cta.b64 P1, [%0], %1, 0x989680;\n\t" \
        "@P1 bra.uni WAIT_DONE_%=;\n\t" \
        "bra.uni WAIT_LOOP_%=;\n\t" \
        "WAIT_DONE_%=:\n\t}" :: "r"(mb), "r"((uint32_t)(ph)) : "memory"); \
} while (0)
__device__ __forceinline__ void bulk_g2s(uint32_t dst, const void* src,
                                         uint32_t bytes, uint32_t mb) {
    asm volatile(
        "cp.async.bulk.shared::cluster.global.mbarrier::complete_tx::bytes [%0], [%1], %2, [%3];"
        :: "r"(dst), "l"(src), "r"(bytes), "r"(mb) : "memory");
}
__device__ __forceinline__ void mma8(float* d, const uint32_t* a, uint32_t b0, uint32_t b1) {
    asm("mma.sync.aligned.m16n8k8.row.col.f32.tf32.tf32.f32 "
        "{%0,%1,%2,%3}, {%4,%5,%6,%7}, {%8,%9}, {%0,%1,%2,%3};"
        : "+f"(d[0]), "+f"(d[1]), "+f"(d[2]), "+f"(d[3])
        : "r"(a[0]), "r"(a[1]), "r"(a[2]), "r"(a[3]), "r"(b0), "r"(b1));
}

// ---------------------------------------------------------------------------
// cvt_pack: blocks [0,384): v1 -> g_v1p4.  blocks [384,672): lin_W -> g_lwp
// (padded chunk-major). Zeroes cbar.
// ---------------------------------------------------------------------------
__global__ __launch_bounds__(256)
void cvt_pack_kernel(const float* __restrict__ v1, const float* __restrict__ linW) {
    const int bid = blockIdx.x, tid = threadIdx.x;
    if (bid < 384) {
        const int idx = bid * 256 + tid;
        const int rb = idx / A4_CNT, rem = idx - rb * A4_CNT;
        const int ks = rem >> 6, p = (rem >> 2) & 15, t4 = rem & 3;
        const int r = rb * 32 + (p & 7) + ((p >> 3) << 4);
        const int k0 = ks * 8 + t4;
        const float* s0 = v1 + r * DIMN + k0;
        const float* s1 = s0 + 8 * DIMN;
        g_v1p4[idx] = make_uint4(f2tf32(s0[0]), f2tf32(s0[4]),
                                 f2tf32(s1[0]), f2tf32(s1[4]));
        if (idx < DIMN) g_cbar[idx] = 0.f;
    } else {
        const int idx = (bid - 384) * 256 + tid;
        const int row = idx / NP, s = idx - row * NP;
        const int k0 = (s >> 2) * 8 + (s & 3);
        const float* src = linW + row * DIMN + k0;
        const int nblk = row >> 5, rloc = row & 31;
        const int chunk = s / 48, sloc = s - chunk * 48;
        g_lwp[((nblk * 4 + chunk) * 32 + rloc) * PSB + sloc] =
            make_uint2(f2tf32(src[0]), f2tf32(src[4]));
    }
}

// ---------------------------------------------------------------------------
// prep: per 32x32 tile: p = prod(1-W_k), c = chain bias.
// g_Ptp (padded chunk-major) gets rw[i]*p transposed; cbar[j] += rw[i]*c.
// ---------------------------------------------------------------------------
__global__ __launch_bounds__(256)
void prep_kernel(const float* __restrict__ W, const float* __restrict__ Bb,
                 const float* __restrict__ rw, int nblocks) {
    __shared__ float pt[32][33];
    __shared__ float cp[32][33];
    const int tid = threadIdx.x;
    const int bi = blockIdx.x, bj = blockIdx.y;
    const int il = tid >> 3, j4 = (tid & 7) * 4;
    const int gi = bi * 32 + il, gj = bj * 32 + j4;

    float4 p = make_float4(1.f, 1.f, 1.f, 1.f);
    float4 c = make_float4(0.f, 0.f, 0.f, 0.f);
    for (int k = 0; k < nblocks; k++) {
        float4 w = *(const float4*)&W[(size_t)k * DIMN * DIMN + gi * DIMN + gj];
        float4 b = *(const float4*)&Bb[(size_t)k * DIMN * DIMN + gi * DIMN + gj];
        float4 om = make_float4(1.f - w.x, 1.f - w.y, 1.f - w.z, 1.f - w.w);
        p.x *= om.x; p.y *= om.y; p.z *= om.z; p.w *= om.w;
        c.x = c.x * om.x + b.x; c.y = c.y * om.y + b.y;
        c.z = c.z * om.z + b.z; c.w = c.w * om.w + b.w;
    }
    const float ri = rw[gi];
    pt[il][j4] = ri * p.x; pt[il][j4 + 1] = ri * p.y;
    pt[il][j4 + 2] = ri * p.z; pt[il][j4 + 3] = ri * p.w;
    cp[il][j4] = ri * c.x; cp[il][j4 + 1] = ri * c.y;
    cp[il][j4 + 2] = ri * c.z; cp[il][j4 + 3] = ri * c.w;
    __syncthreads();

    if (tid < 32) {
        float s = 0.f;
#pragma unroll
        for (int i = 0; i < 32; i++) s += cp[i][tid];
        atomicAdd(&g_cbar[bj * 32 + tid], s);
    }
#pragma unroll
    for (int q = tid; q < 512; q += 256) {
        int j = q >> 4, s = q & 15;
        int i0 = (s >> 2) * 8 + (s & 3);
        int dst = ((bj * 4 + bi / 3) * 32 + j) * PSB + (bi % 3) * 16 + s;
        g_Ptp[dst] = make_uint2(f2tf32(pt[i0][j]), f2tf32(pt[i0 + 4][j]));
    }
}

// ---------------------------------------------------------------------------
// gemm tile body (identical math to the 21.0us R12 kernel)
// ---------------------------------------------------------------------------
template <int MODE>
__device__ void gemm_tile(char* smc, uint32_t sbase, uint32_t mb0,
                          int nx, int rb,
                          const uint4* __restrict__ Ap4,
                          const uint2* __restrict__ Bp,
                          const float* __restrict__ v2,
                          const float* __restrict__ cbar,
                          const float* __restrict__ linb,
                          float* __restrict__ Out) {
    const int tid = threadIdx.x, lane = tid & 31, wid = tid >> 5;
    const int g = lane >> 2, t4 = lane & 3;
    const int wn = wid & 1, kh = wid >> 1;
    const int m0 = rb * 32, n0 = nx * 32;

    const char* aSrc = (const char*)(Ap4 + (size_t)rb * A4_CNT);
    const char* bSrc = (const char*)(Bp + (size_t)nx * 4 * BPAD_CHUNK);

    auto issueChunk = [&](int c, int buf) {
        const uint32_t mb = mb0 + buf * 8;
        mbar_expect(mb, STAGE_B);
        bulk_g2s(sbase + buf * STAGE_B, aSrc + c * ABYTES_C, ABYTES_C, mb);
        bulk_g2s(sbase + buf * STAGE_B + ABYTES_C, bSrc + c * BBYTES_C, BBYTES_C, mb);
    };

    if (tid == 0) { issueChunk(0, 0); issueChunk(1, 1); }

    float acc[2][2][4] = {};

#pragma unroll
    for (int c = 0; c < 4; c++) {
        const int buf = c & 1;
        MBAR_WAIT(mb0 + buf * 8, c >> 1);

        const uint4* A4b = (const uint4*)(smc + buf * STAGE_B);
        const uint2* Bsb = (const uint2*)(smc + buf * STAGE_B + ABYTES_C);
        const uint4* aP = &A4b[kh * 3 * 64 + g * 4 + t4];
        const uint2* bP = &Bsb[(wn * 16 + g) * PSB + kh * 12 + t4];
#pragma unroll
        for (int l = 0; l < 3; l++) {
            uint4 qa0 = aP[l * 64], qa1 = aP[l * 64 + 32];
            uint2 qb0 = bP[l * 4],  qb1 = bP[8 * PSB + l * 4];
            uint32_t a0[4] = {qa0.x, qa0.z, qa0.y, qa0.w};
            uint32_t a1[4] = {qa1.x, qa1.z, qa1.y, qa1.w};
            mma8(acc[0][0], a0, qb0.x, qb0.y);
            mma8(acc[0][1], a0, qb1.x, qb1.y);
            mma8(acc[1][0], a1, qb0.x, qb0.y);
            mma8(acc[1][1], a1, qb1.x, qb1.y);
        }
        __syncthreads();
        if (c < 2 && tid == 0) issueChunk(c + 2, buf);
    }

    // cross-quarter reduction via smem (reuse ring region)
    float* red = (float*)smc;
    if (kh > 0) {
        float* r = red + (kh - 1) * (32 * 34);
#pragma unroll
        for (int mi = 0; mi < 2; mi++) {
            const int rl = mi * 16 + g;
#pragma unroll
            for (int nf = 0; nf < 2; nf++) {
                const int cc = wn * 16 + nf * 8 + 2 * t4;
                *(float2*)&r[rl * 34 + cc]       = make_float2(acc[mi][nf][0], acc[mi][nf][1]);
                *(float2*)&r[(rl + 8) * 34 + cc] = make_float2(acc[mi][nf][2], acc[mi][nf][3]);
            }
        }
    }
    __syncthreads();
    if (kh > 0) return;

#pragma unroll
    for (int b = 0; b < 3; b++) {
        const float* r = red + b * (32 * 34);
#pragma unroll
        for (int mi = 0; mi < 2; mi++) {
            const int rl = mi * 16 + g;
#pragma unroll
            for (int nf = 0; nf < 2; nf++) {
                const int cc = wn * 16 + nf * 8 + 2 * t4;
                float2 p0 = *(const float2*)&r[rl * 34 + cc];
                float2 p1 = *(const float2*)&r[(rl + 8) * 34 + cc];
                acc[mi][nf][0] += p0.x; acc[mi][nf][1] += p0.y;
                acc[mi][nf][2] += p1.x; acc[mi][nf][3] += p1.y;
            }
        }
    }

#pragma unroll
    for (int mi = 0; mi < 2; mi++) {
        const int r0 = m0 + mi * 16 + g, r1 = r0 + 8;
#pragma unroll
        for (int nf = 0; nf < 2; nf++) {
            const int C = n0 + wn * 16 + nf * 8 + 2 * t4;
            if (MODE == 0) {
                float2 cb = *(const float2*)&cbar[C];
                float2 va = *(const float2*)&v2[r0 * DIMN + C];
                float2 vb = *(const float2*)&v2[r1 * DIMN + C];
                float c0 = va.x * acc[mi][nf][0] - cb.x;
                float c1 = va.y * acc[mi][nf][1] - cb.y;
                float c2 = vb.x * acc[mi][nf][2] - cb.x;
                float c3 = vb.y * acc[mi][nf][3] - cb.y;
                float u0 = __shfl_down_sync(0xffffffffu, c0, 2);
                float u1 = __shfl_down_sync(0xffffffffu, c1, 2);
                float u2 = __shfl_down_sync(0xffffffffu, c2, 2);
                float u3 = __shfl_down_sync(0xffffffffu, c3, 2);
                if (t4 < 2) {
                    const int p = mi * 8 + g;
                    const int ks_g = (n0 + wn * 16 + nf * 8) >> 3;
                    size_t base = (size_t)rb * A4_CNT + ks_g * 64 + p * 4;
                    g_tp4[base + 2 * t4] =
                        make_uint4(f2tf32(c0), f2tf32(u0), f2tf32(c2), f2tf32(u2));
                    g_tp4[base + 2 * t4 + 1] =
                        make_uint4(f2tf32(c1), f2tf32(u1), f2tf32(c3), f2tf32(u3));
                }
            } else {
                float2 lb = *(const float2*)&linb[C];
                *(float2*)&Out[r0 * DIMN + C] =
                    make_float2(acc[mi][nf][0] + lb.x, acc[mi][nf][1] + lb.y);
                *(float2*)&Out[r1 * DIMN + C] =
                    make_float2(acc[mi][nf][2] + lb.x, acc[mi][nf][3] + lb.y);
            }
        }
    }
}

// ---------------------------------------------------------------------------
// Fused gemm pair: 768 CTAs. bid<384 -> gemm0 tile, signal g0done[rb].
// bid>=384 -> wait for its rb's 12 gemm0 tiles (epoch via monotonic ticket),
// then gemm1 tile. 4 CTAs/SM resident (592) >= 384 producers -> no deadlock.
// ---------------------------------------------------------------------------
__global__ __launch_bounds__(256, 4)
void gemm_pair_kernel(const float* __restrict__ v2,
                      const float* __restrict__ linb,
                      float* __restrict__ out) {
    extern __shared__ __align__(16) char smc[];
    __shared__ __align__(8) uint64_t mbar_sh[2];
    const int bid = blockIdx.x, tid = threadIdx.x;

    const uint32_t sbase = smem_u32(smc);
    const uint32_t mb0 = smem_u32(mbar_sh);
    if (tid == 0) { mbar_init(mb0, 1); mbar_init(mb0 + 8, 1); }
    __syncthreads();

    if (bid < 384) {
        const int nx = bid % 12, rb = bid / 12;
        gemm_tile<0>(smc, sbase, mb0, nx, rb, g_v1p4, g_Ptp,
                     v2, g_cbar, nullptr, nullptr);
        __syncthreads();                    // epilogue STGs done
        if (tid == 0) {
            __threadfence();                // release g_tp4
            atomicAdd(&g_g0done[rb], 1ULL);
        }
    } else {
        const int b2 = bid - 384;
        const int nx = b2 % 12, rb = b2 / 12;
        if (tid == 0) {
            unsigned long long t = atomicAdd(&g_g1arr[rb], 1ULL);
            unsigned long long target = (t / 12ULL + 1ULL) * 12ULL;
            while (*(volatile unsigned long long*)&g_g0done[rb] < target)
                __nanosleep(128);
            __threadfence();                // acquire
        }
        __syncthreads();
        gemm_tile<1>(smc, sbase, mb0, nx, rb, g_tp4, g_lwp,
                     nullptr, nullptr, linb, out);
    }
}

// ---------------------------------------------------------------------------
// Launch. Inputs: v1, v2, block_W, block_b, row_weights, lin_W, lin_b
// ---------------------------------------------------------------------------
extern "C" void kernel_launch(void* const* d_in, const int* in_sizes, int n_in,
                              void* d_out, int out_size) {
    const float* v1   = (const float*)d_in[0];
    const float* v2   = (const float*)d_in[1];
    const float* bW   = (const float*)d_in[2];
    const float* bB   = (const float*)d_in[3];
    const float* rw   = (const float*)d_in[4];
    const float* linW = (const float*)d_in[5];
    const float* linb = (const float*)d_in[6];

    const int nblocks = in_sizes[2] / (DIMN * DIMN);

    cudaFuncSetAttribute(gemm_pair_kernel,
                         cudaFuncAttributeMaxDynamicSharedMemorySize, SMEM_GEMM);

    cvt_pack_kernel<<<672, 256>>>(v1, linW);
    prep_kernel<<<dim3(12, 12), 256>>>(bW, bB, rw, nblocks);
    gemm_pair_kernel<<<768, 256, SMEM_GEMM>>>(v2, linb, (float*)d_out);
}

// round 16
// speedup vs baseline: 1.0992x; 1.0992x over previous
#include <cuda_runtime.h>
#include <cstdint>

#define DIMN 384
#define NP 192                    // logical uint2 slots per B row (full K)
#define PSB 52                    // B pitch in uint2 (48 data + 4 pad)
#define A4_CNT 3072               // uint4 per 32-row A block (full K)
#define A4_PER_CHUNK 768          // uint4 per K=96 chunk
#define ABYTES_C (A4_PER_CHUNK * 16)      // 12288
#define BPAD_CHUNK (32 * PSB)
#define BBYTES_C (BPAD_CHUNK * 8) // 13312
#define STAGE_B (ABYTES_C + BBYTES_C)     // 25600
#define SMEM_GEMM (2 * STAGE_B)   // 51200 -> 4 CTAs/SM
#define FP4PITCH 97               // staged row pitch in float4 (96 data + 1 pad)
#define SMEM_PACK (32 * FP4PITCH * 16)    // 49664

// Scratch (no cudaMalloc allowed)
__device__ __align__(16) uint4 g_v1p4[32 * A4_CNT];
__device__ __align__(16) uint4 g_tp4[32 * A4_CNT];
__device__ __align__(16) uint2 g_lwp[12 * 4 * BPAD_CHUNK];
__device__ __align__(16) uint2 g_Ptp[12 * 4 * BPAD_CHUNK];
__device__ float g_cbarp[12][DIMN];       // racefree per-bi cbar partials

__device__ __forceinline__ uint32_t f2tf32(float x) {
    uint32_t y; asm("cvt.rna.tf32.f32 %0, %1;" : "=r"(y) : "f"(x)); return y;
}
__device__ __forceinline__ uint32_t smem_u32(const void* p) {
    uint32_t a;
    asm("{ .reg .u64 t; cvta.to.shared.u64 t, %1; cvt.u32.u64 %0, t; }" : "=r"(a) : "l"(p));
    return a;
}
__device__ __forceinline__ void mbar_init(uint32_t mb, uint32_t cnt) {
    asm volatile("mbarrier.init.shared.b64 [%0], %1;" :: "r"(mb), "r"(cnt) : "memory");
}
__device__ __forceinline__ void mbar_expect(uint32_t mb, uint32_t tx) {
    asm volatile("mbarrier.arrive.expect_tx.shared.b64 _, [%0], %1;" :: "r"(mb), "r"(tx) : "memory");
}
#define MBAR_WAIT(mb, ph) do { \
    asm volatile("{\n\t.reg .pred P1;\n\t" \
        "WAIT_LOOP_%=:\n\t" \
        "mbarrier.try_wait.parity.acquire.cta.shared::cta.b64 P1, [%0], %1, 0x989680;\n\t" \
        "@P1 bra.uni WAIT_DONE_%=;\n\t" \
        "bra.uni WAIT_LOOP_%=;\n\t" \
        "WAIT_DONE_%=:\n\t}" :: "r"(mb), "r"((uint32_t)(ph)) : "memory"); \
} while (0)
__device__ __forceinline__ void bulk_g2s(uint32_t dst, const void* src,
                                         uint32_t bytes, uint32_t mb) {
    asm volatile(
        "cp.async.bulk.shared::cluster.global.mbarrier::complete_tx::bytes [%0], [%1], %2, [%3];"
        :: "r"(dst), "l"(src), "r"(bytes), "r"(mb) : "memory");
}
__device__ __forceinline__ void mma8(float* d, const uint32_t* a, uint32_t b0, uint32_t b1) {
    asm("mma.sync.aligned.m16n8k8.row.col.f32.tf32.tf32.f32 "
        "{%0,%1,%2,%3}, {%4,%5,%6,%7}, {%8,%9}, {%0,%1,%2,%3};"
        : "+f"(d[0]), "+f"(d[1]), "+f"(d[2]), "+f"(d[3])
        : "r"(a[0]), "r"(a[1]), "r"(a[2]), "r"(a[3]), "r"(b0), "r"(b1));
}

// ---------------------------------------------------------------------------
// pack_prep: one launch, three independent block roles.
//   bid <  144: prep tile (bi,bj) -> g_Ptp + g_cbarp[bi] (racefree stores)
//   144..175  : v1 pack rb = bid-144 (smem-staged, coalesced both ways)
//   176..187  : linW pack nb = bid-176
// ---------------------------------------------------------------------------
__global__ __launch_bounds__(256)
void pack_prep_kernel(const float* __restrict__ v1, const float* __restrict__ linW,
                      const float* __restrict__ W, const float* __restrict__ Bb,
                      const float* __restrict__ rw, int nblocks) {
    extern __shared__ __align__(16) char smc[];
    const int bid = blockIdx.x, tid = threadIdx.x;

    if (bid < 144) {
        // ---- prep tile ----
        float* pt = (float*)smc;           // 32 x 33
        float* cp = pt + 32 * 33;
        const int bi = bid % 12, bj = bid / 12;
        const int il = tid >> 3, j4 = (tid & 7) * 4;
        const int gi = bi * 32 + il, gj = bj * 32 + j4;

        float4 p = make_float4(1.f, 1.f, 1.f, 1.f);
        float4 c = make_float4(0.f, 0.f, 0.f, 0.f);
        for (int k = 0; k < nblocks; k++) {
            float4 w = *(const float4*)&W[(size_t)k * DIMN * DIMN + gi * DIMN + gj];
            float4 b = *(const float4*)&Bb[(size_t)k * DIMN * DIMN + gi * DIMN + gj];
            float4 om = make_float4(1.f - w.x, 1.f - w.y, 1.f - w.z, 1.f - w.w);
            p.x *= om.x; p.y *= om.y; p.z *= om.z; p.w *= om.w;
            c.x = c.x * om.x + b.x; c.y = c.y * om.y + b.y;
            c.z = c.z * om.z + b.z; c.w = c.w * om.w + b.w;
        }
        const float ri = rw[gi];
        pt[il * 33 + j4] = ri * p.x; pt[il * 33 + j4 + 1] = ri * p.y;
        pt[il * 33 + j4 + 2] = ri * p.z; pt[il * 33 + j4 + 3] = ri * p.w;
        cp[il * 33 + j4] = ri * c.x; cp[il * 33 + j4 + 1] = ri * c.y;
        cp[il * 33 + j4 + 2] = ri * c.z; cp[il * 33 + j4 + 3] = ri * c.w;
        __syncthreads();

        if (tid < 32) {
            float s = 0.f;
#pragma unroll
            for (int i = 0; i < 32; i++) s += cp[i * 33 + tid];
            g_cbarp[bi][bj * 32 + tid] = s;    // plain store, racefree
        }
#pragma unroll
        for (int q = tid; q < 512; q += 256) {
            int j = q >> 4, s = q & 15;
            int i0 = (s >> 2) * 8 + (s & 3);
            int dst = ((bj * 4 + bi / 3) * 32 + j) * PSB + (bi % 3) * 16 + s;
            g_Ptp[dst] = make_uint2(f2tf32(pt[i0 * 33 + j]),
                                    f2tf32(pt[(i0 + 4) * 33 + j]));
        }
    } else if (bid < 176) {
        // ---- v1 pack, rb = bid-144: stage 32 raw rows, emit packed uint4 ----
        const int rb = bid - 144;
        float4* stg = (float4*)smc;
        float* stf = (float*)smc;
#pragma unroll
        for (int j = 0; j < 12; j++) {
            int t = tid + j * 256;             // 0..3071
            int row = t / 96, c4 = t - row * 96;
            stg[row * FP4PITCH + c4] =
                *(const float4*)&v1[(size_t)(rb * 32 + row) * DIMN + c4 * 4];
        }
        __syncthreads();
#pragma unroll
        for (int j = 0; j < 12; j++) {
            int rem = tid + j * 256;
            int ks = rem >> 6, p = (rem >> 2) & 15, t4 = rem & 3;
            int rloc = (p & 7) + ((p >> 3) << 4);
            int k0 = ks * 8 + t4;
            const float* r0 = stf + rloc * (FP4PITCH * 4);
            const float* r1 = r0 + 8 * (FP4PITCH * 4);
            g_v1p4[rb * A4_CNT + rem] =
                make_uint4(f2tf32(r0[k0]), f2tf32(r0[k0 + 4]),
                           f2tf32(r1[k0]), f2tf32(r1[k0 + 4]));
        }
    } else {
        // ---- linW pack, nb = bid-176: stage 32 rows, emit padded chunk-major
        const int nb = bid - 176;
        float4* stg = (float4*)smc;
        float* stf = (float*)smc;
#pragma unroll
        for (int j = 0; j < 12; j++) {
            int t = tid + j * 256;
            int row = t / 96, c4 = t - row * 96;
            stg[row * FP4PITCH + c4] =
                *(const float4*)&linW[(size_t)(nb * 32 + row) * DIMN + c4 * 4];
        }
        __syncthreads();
#pragma unroll
        for (int j = 0; j < 24; j++) {
            int q = tid + j * 256;             // 0..6143
            int row = q / NP, s = q - row * NP;
            int k0 = (s >> 2) * 8 + (s & 3);
            int chunk = s / 48, sloc = s - chunk * 48;
            const float* r0 = stf + row * (FP4PITCH * 4);
            g_lwp[((nb * 4 + chunk) * 32 + row) * PSB + sloc] =
                make_uint2(f2tf32(r0[k0]), f2tf32(r0[k0 + 4]));
        }
    }
}

// ---------------------------------------------------------------------------
// tf32 mma.sync GEMM (proven R13 body). 32x32 tile, 8 warps = wn(2) x kh(4),
// K = 4 chunks of 96, 2-stage bulk-copy ring, cross-quarter smem reduction.
// MODE 0: t = v2 .* (v1 @ rwP) - sum(cbarp)  -> g_tp4 (packed)
// MODE 1: out = (t @ linW^T) + linb          -> f32 Out
// ---------------------------------------------------------------------------
template <int MODE>
__global__ __launch_bounds__(256, 4)
void mma_gemm(const uint4* __restrict__ Ap4, const uint2* __restrict__ Bp,
              const float* __restrict__ v2, const float* __restrict__ linb,
              float* __restrict__ Out) {
    extern __shared__ __align__(16) char smc[];
    __shared__ __align__(8) uint64_t mbar_sh[2];

    const int tid = threadIdx.x, lane = tid & 31, wid = tid >> 5;
    const int g = lane >> 2, t4 = lane & 3;
    const int wn = wid & 1, kh = wid >> 1;
    const int rb = blockIdx.y, nx = blockIdx.x;
    const int m0 = rb * 32, n0 = nx * 32;

    const uint32_t sbase = smem_u32(smc);
    const uint32_t mb0 = smem_u32(mbar_sh);
    const char* aSrc = (const char*)(Ap4 + (size_t)rb * A4_CNT);
    const char* bSrc = (const char*)(Bp + (size_t)nx * 4 * BPAD_CHUNK);

    if (tid == 0) { mbar_init(mb0, 1); mbar_init(mb0 + 8, 1); }
    __syncthreads();

    auto issueChunk = [&](int c, int buf) {
        const uint32_t mb = mb0 + buf * 8;
        mbar_expect(mb, STAGE_B);
        bulk_g2s(sbase + buf * STAGE_B, aSrc + c * ABYTES_C, ABYTES_C, mb);
        bulk_g2s(sbase + buf * STAGE_B + ABYTES_C, bSrc + c * BBYTES_C, BBYTES_C, mb);
    };

    if (tid == 0) { issueChunk(0, 0); issueChunk(1, 1); }

    float acc[2][2][4] = {};

#pragma unroll
    for (int c = 0; c < 4; c++) {
        const int buf = c & 1;
        MBAR_WAIT(mb0 + buf * 8, c >> 1);

        const uint4* A4b = (const uint4*)(smc + buf * STAGE_B);
        const uint2* Bsb = (const uint2*)(smc + buf * STAGE_B + ABYTES_C);
        const uint4* aP = &A4b[kh * 3 * 64 + g * 4 + t4];
        const uint2* bP = &Bsb[(wn * 16 + g) * PSB + kh * 12 + t4];
#pragma unroll
        for (int l = 0; l < 3; l++) {
            uint4 qa0 = aP[l * 64], qa1 = aP[l * 64 + 32];
            uint2 qb0 = bP[l * 4],  qb1 = bP[8 * PSB + l * 4];
            uint32_t a0[4] = {qa0.x, qa0.z, qa0.y, qa0.w};
            uint32_t a1[4] = {qa1.x, qa1.z, qa1.y, qa1.w};
            mma8(acc[0][0], a0, qb0.x, qb0.y);
            mma8(acc[0][1], a0, qb1.x, qb1.y);
            mma8(acc[1][0], a1, qb0.x, qb0.y);
            mma8(acc[1][1], a1, qb1.x, qb1.y);
        }
        __syncthreads();
        if (c < 2 && tid == 0) issueChunk(c + 2, buf);
    }

    // cross-quarter reduction via smem (reuse ring region)
    float* red = (float*)smc;
    if (kh > 0) {
        float* r = red + (kh - 1) * (32 * 34);
#pragma unroll
        for (int mi = 0; mi < 2; mi++) {
            const int rl = mi * 16 + g;
#pragma unroll
            for (int nf = 0; nf < 2; nf++) {
                const int cc = wn * 16 + nf * 8 + 2 * t4;
                *(float2*)&r[rl * 34 + cc]       = make_float2(acc[mi][nf][0], acc[mi][nf][1]);
                *(float2*)&r[(rl + 8) * 34 + cc] = make_float2(acc[mi][nf][2], acc[mi][nf][3]);
            }
        }
    }
    __syncthreads();
    if (kh > 0) return;

#pragma unroll
    for (int b = 0; b < 3; b++) {
        const float* r = red + b * (32 * 34);
#pragma unroll
        for (int mi = 0; mi < 2; mi++) {
            const int rl = mi * 16 + g;
#pragma unroll
            for (int nf = 0; nf < 2; nf++) {
                const int cc = wn * 16 + nf * 8 + 2 * t4;
                float2 p0 = *(const float2*)&r[rl * 34 + cc];
                float2 p1 = *(const float2*)&r[(rl + 8) * 34 + cc];
                acc[mi][nf][0] += p0.x; acc[mi][nf][1] += p0.y;
                acc[mi][nf][2] += p1.x; acc[mi][nf][3] += p1.y;
            }
        }
    }

#pragma unroll
    for (int mi = 0; mi < 2; mi++) {
        const int r0 = m0 + mi * 16 + g, r1 = r0 + 8;
#pragma unroll
        for (int nf = 0; nf < 2; nf++) {
            const int C = n0 + wn * 16 + nf * 8 + 2 * t4;
            if (MODE == 0) {
                float2 cb = make_float2(0.f, 0.f);
#pragma unroll
                for (int b = 0; b < 12; b++) {
                    float2 p = *(const float2*)&g_cbarp[b][C];
                    cb.x += p.x; cb.y += p.y;
                }
                float2 va = *(const float2*)&v2[r0 * DIMN + C];
                float2 vb = *(const float2*)&v2[r1 * DIMN + C];
                float c0 = va.x * acc[mi][nf][0] - cb.x;
                float c1 = va.y * acc[mi][nf][1] - cb.y;
                float c2 = vb.x * acc[mi][nf][2] - cb.x;
                float c3 = vb.y * acc[mi][nf][3] - cb.y;
                float u0 = __shfl_down_sync(0xffffffffu, c0, 2);
                float u1 = __shfl_down_sync(0xffffffffu, c1, 2);
                float u2 = __shfl_down_sync(0xffffffffu, c2, 2);
                float u3 = __shfl_down_sync(0xffffffffu, c3, 2);
                if (t4 < 2) {
                    const int p = mi * 8 + g;
                    const int ks_g = (n0 + wn * 16 + nf * 8) >> 3;
                    size_t base = (size_t)rb * A4_CNT + ks_g * 64 + p * 4;
                    g_tp4[base + 2 * t4] =
                        make_uint4(f2tf32(c0), f2tf32(u0), f2tf32(c2), f2tf32(u2));
                    g_tp4[base + 2 * t4 + 1] =
                        make_uint4(f2tf32(c1), f2tf32(u1), f2tf32(c3), f2tf32(u3));
                }
            } else {
                float2 lb = *(const float2*)&linb[C];
                *(float2*)&Out[r0 * DIMN + C] =
                    make_float2(acc[mi][nf][0] + lb.x, acc[mi][nf][1] + lb.y);
                *(float2*)&Out[r1 * DIMN + C] =
                    make_float2(acc[mi][nf][2] + lb.x, acc[mi][nf][3] + lb.y);
            }
        }
    }
}

// ---------------------------------------------------------------------------
// Launch. Inputs: v1, v2, block_W, block_b, row_weights, lin_W, lin_b
// ---------------------------------------------------------------------------
extern "C" void kernel_launch(void* const* d_in, const int* in_sizes, int n_in,
                              void* d_out, int out_size) {
    const float* v1   = (const float*)d_in[0];
    const float* v2   = (const float*)d_in[1];
    const float* bW   = (const float*)d_in[2];
    const float* bB   = (const float*)d_in[3];
    const float* rw   = (const float*)d_in[4];
    const float* linW = (const float*)d_in[5];
    const float* linb = (const float*)d_in[6];

    const int nblocks = in_sizes[2] / (DIMN * DIMN);

    uint4 *gv1p4, *gtp4; uint2 *glwp, *gPtp;
    cudaGetSymbolAddress((void**)&gv1p4, g_v1p4);
    cudaGetSymbolAddress((void**)&gtp4,  g_tp4);
    cudaGetSymbolAddress((void**)&glwp,  g_lwp);
    cudaGetSymbolAddress((void**)&gPtp,  g_Ptp);

    cudaFuncSetAttribute(pack_prep_kernel,
                         cudaFuncAttributeMaxDynamicSharedMemorySize, SMEM_PACK);
    cudaFuncSetAttribute(mma_gemm<0>,
                         cudaFuncAttributeMaxDynamicSharedMemorySize, SMEM_GEMM);
    cudaFuncSetAttribute(mma_gemm<1>,
                         cudaFuncAttributeMaxDynamicSharedMemorySize, SMEM_GEMM);

    pack_prep_kernel<<<188, 256, SMEM_PACK>>>(v1, linW, bW, bB, rw, nblocks);
    dim3 grid(12, 32);
    mma_gemm<0><<<grid, 256, SMEM_GEMM>>>(gv1p4, gPtp, v2, nullptr, nullptr);
    mma_gemm<1><<<grid, 256, SMEM_GEMM>>>(gtp4, glwp, nullptr, linb, (float*)d_out);
}